// round 2
// baseline (speedup 1.0000x reference)
#include <cuda_runtime.h>

#define HIST_N   65536
#define SUB_N    8192
#define SUB_SHIFT 6
#define MARGIN   4

// Scratch (device globals: no allocation allowed)
__device__ unsigned int       g_hist[HIST_N];
__device__ unsigned int       g_sub[SUB_N];
__device__ double             g_sum;
__device__ unsigned long long g_cnt;
__device__ unsigned int       g_ctrl[4]; // [0]=base_bits, [1]=hi_bits, [2]=nsub

__device__ __forceinline__ float bce_loss(float x, float t) {
    float a  = fabsf(x);
    float sp = log1pf(__expf(-a));
    float l  = fmaxf(x, 0.0f) - x * t + sp;
    return fmaxf(l, 0.0f);   // guard against -0/rounding; keeps bits monotone
}

// ---------------- K0: zero scratch ----------------
__global__ void k_zero() {
    int i  = blockIdx.x * blockDim.x + threadIdx.x;
    int nt = gridDim.x * blockDim.x;
    for (int j = i; j < HIST_N; j += nt) g_hist[j] = 0u;
    for (int j = i; j < SUB_N;  j += nt) g_sub[j]  = 0u;
    if (i == 0) { g_sum = 0.0; g_cnt = 0ull; }
}

// ---------------- K1: sampled histogram (1/8 of float4 chunks) ----------------
__global__ void k_sample(const float4* __restrict__ p, const float4* __restrict__ t,
                         long long n4) {
    long long stride = (long long)gridDim.x * blockDim.x;
    for (long long j = blockIdx.x * (long long)blockDim.x + threadIdx.x;
         j * 8 < n4; j += stride) {
        long long idx = j * 8;
        float4 xp = p[idx];
        float4 xt = t[idx];
        unsigned b;
        b = __float_as_uint(bce_loss(xp.x, xt.x)) >> 15; atomicAdd(&g_hist[b], 1u);
        b = __float_as_uint(bce_loss(xp.y, xt.y)) >> 15; atomicAdd(&g_hist[b], 1u);
        b = __float_as_uint(bce_loss(xp.z, xt.z)) >> 15; atomicAdd(&g_hist[b], 1u);
        b = __float_as_uint(bce_loss(xp.w, xt.w)) >> 15; atomicAdd(&g_hist[b], 1u);
    }
}

// ---------------- K2: find sample quantile bucket, set window ----------------
__global__ void __launch_bounds__(1024) k_select(unsigned long long ks) {
    __shared__ unsigned long long suf[1024];
    __shared__ int s_chunk;
    __shared__ unsigned long long s_tail;
    int tid = threadIdx.x;

    unsigned long long s = 0;
    int cbase = tid * 64;
    #pragma unroll 8
    for (int j = 0; j < 64; j++) s += g_hist[cbase + j];
    suf[tid] = s;
    __syncthreads();
    // inclusive suffix scan over 1024 chunk sums
    for (int off = 1; off < 1024; off <<= 1) {
        unsigned long long add = (tid + off < 1024) ? suf[tid + off] : 0ull;
        __syncthreads();
        suf[tid] += add;
        __syncthreads();
    }
    unsigned long long nxt = (tid < 1023) ? suf[tid + 1] : 0ull;
    if (suf[tid] >= ks && nxt < ks) { s_chunk = tid; s_tail = nxt; }
    __syncthreads();

    if (tid == 0) {
        int chunk = s_chunk;
        unsigned long long cum = s_tail;
        int bstar = chunk * 64;
        for (int j = 63; j >= 0; j--) {
            cum += g_hist[chunk * 64 + j];
            if (cum >= ks) { bstar = chunk * 64 + j; break; }
        }
        unsigned blo = (bstar >= MARGIN) ? (unsigned)(bstar - MARGIN) : 0u;
        unsigned bhi = (bstar + MARGIN <= 65535) ? (unsigned)(bstar + MARGIN) : 65535u;
        g_ctrl[0] = blo << 15;
        g_ctrl[1] = (bhi + 1u) << 15;
        g_ctrl[2] = ((bhi - blo + 1u) << 15) >> SUB_SHIFT;
    }
}

// ---------------- K3: main exact pass ----------------
__global__ void __launch_bounds__(512) k_main(const float4* __restrict__ p,
                                              const float4* __restrict__ t,
                                              long long n4, long long n) {
    const unsigned base = g_ctrl[0];
    const unsigned hi   = g_ctrl[1];
    double   lsum = 0.0;
    unsigned lcnt = 0u;

    long long stride = (long long)gridDim.x * blockDim.x;
    for (long long i = blockIdx.x * (long long)blockDim.x + threadIdx.x;
         i < n4; i += stride) {
        float4 xp = p[i];
        float4 xt = t[i];
        float v; unsigned b;
        v = bce_loss(xp.x, xt.x); b = __float_as_uint(v);
        if (b >= hi) { lsum += v; lcnt++; }
        else if (b >= base) atomicAdd(&g_sub[(b - base) >> SUB_SHIFT], 1u);
        v = bce_loss(xp.y, xt.y); b = __float_as_uint(v);
        if (b >= hi) { lsum += v; lcnt++; }
        else if (b >= base) atomicAdd(&g_sub[(b - base) >> SUB_SHIFT], 1u);
        v = bce_loss(xp.z, xt.z); b = __float_as_uint(v);
        if (b >= hi) { lsum += v; lcnt++; }
        else if (b >= base) atomicAdd(&g_sub[(b - base) >> SUB_SHIFT], 1u);
        v = bce_loss(xp.w, xt.w); b = __float_as_uint(v);
        if (b >= hi) { lsum += v; lcnt++; }
        else if (b >= base) atomicAdd(&g_sub[(b - base) >> SUB_SHIFT], 1u);
    }
    // scalar tail (n not multiple of 4) — handled by one thread
    if (blockIdx.x == 0 && threadIdx.x == 0) {
        const float* ps = (const float*)p;
        const float* ts = (const float*)t;
        for (long long i = n4 * 4; i < n; i++) {
            float v = bce_loss(ps[i], ts[i]);
            unsigned b = __float_as_uint(v);
            if (b >= hi) { lsum += v; lcnt++; }
            else if (b >= base) atomicAdd(&g_sub[(b - base) >> SUB_SHIFT], 1u);
        }
    }

    // block reduce (16 warps)
    for (int o = 16; o; o >>= 1) {
        lsum += __shfl_down_sync(0xffffffffu, lsum, o);
        lcnt += __shfl_down_sync(0xffffffffu, lcnt, o);
    }
    __shared__ double   ws[16];
    __shared__ unsigned wc[16];
    int wid = threadIdx.x >> 5, lane = threadIdx.x & 31;
    if (lane == 0) { ws[wid] = lsum; wc[wid] = lcnt; }
    __syncthreads();
    if (wid == 0) {
        double   v = (lane < 16) ? ws[lane] : 0.0;
        unsigned c = (lane < 16) ? wc[lane] : 0u;
        for (int o = 8; o; o >>= 1) {
            v += __shfl_down_sync(0xffffffffu, v, o);
            c += __shfl_down_sync(0xffffffffu, c, o);
        }
        if (lane == 0) {
            atomicAdd(&g_sum, v);
            atomicAdd(&g_cnt, (unsigned long long)c);
        }
    }
}

// ---------------- K4: finalize ----------------
__global__ void __launch_bounds__(512) k_final(long long k, float* __restrict__ out) {
    __shared__ unsigned long long sufc[512];
    __shared__ double             sufw[512];
    int tid = threadIdx.x;
    unsigned base = g_ctrl[0];
    int nsub = (int)g_ctrl[2];
    int per  = (nsub + 511) / 512;

    unsigned long long c = 0ull;
    double             w = 0.0;
    for (int j = 0; j < per; j++) {
        int s = tid * per + j;
        if (s < nsub) {
            unsigned cs = g_sub[s];
            c += cs;
            w += (double)cs *
                 (double)__uint_as_float(base + ((unsigned)s << SUB_SHIFT) + (1u << (SUB_SHIFT - 1)));
        }
    }
    sufc[tid] = c; sufw[tid] = w;
    __syncthreads();
    for (int off = 1; off < 512; off <<= 1) {
        unsigned long long ac = (tid + off < 512) ? sufc[tid + off] : 0ull;
        double             aw = (tid + off < 512) ? sufw[tid + off] : 0.0;
        __syncthreads();
        sufc[tid] += ac; sufw[tid] += aw;
        __syncthreads();
    }

    double    sum_gt = g_sum;
    long long cnt    = (long long)g_cnt;
    long long r      = k - cnt;

    if (r <= 0) {  // window was too low: remove |r| elements at the upper edge value
        if (tid == 0) {
            double edge = (double)__uint_as_float(g_ctrl[1]);
            out[0] = (float)((sum_gt + (double)r * edge) / (double)k);
        }
        return;
    }
    if ((unsigned long long)r > sufc[0]) {  // window too high: pad at lower edge value
        if (tid == 0) {
            double res = (sum_gt + sufw[0] +
                          (double)(r - (long long)sufc[0]) * (double)__uint_as_float(base)) /
                         (double)k;
            out[0] = (float)res;
        }
        return;
    }

    unsigned long long nxtc = (tid < 511) ? sufc[tid + 1] : 0ull;
    double             nxtw = (tid < 511) ? sufw[tid + 1] : 0.0;
    if (sufc[tid] >= (unsigned long long)r && nxtc < (unsigned long long)r) {
        unsigned long long cum = nxtc;
        double             acc = nxtw;
        for (int j = per - 1; j >= 0; j--) {
            int s = tid * per + j;
            if (s >= nsub) continue;
            unsigned cs = g_sub[s];
            double mid = (double)__uint_as_float(base + ((unsigned)s << SUB_SHIFT) +
                                                 (1u << (SUB_SHIFT - 1)));
            if (cum + cs >= (unsigned long long)r) {
                acc += (double)((unsigned long long)r - cum) * mid;
                out[0] = (float)((sum_gt + acc) / (double)k);
                break;
            } else {
                acc += (double)cs * mid;
                cum += cs;
            }
        }
    }
}

// ---------------- host ----------------
extern "C" void kernel_launch(void* const* d_in, const int* in_sizes, int n_in,
                              void* d_out, int out_size) {
    const float* pred = (const float*)d_in[0];
    const float* targ = (const float*)d_in[1];
    long long n  = (long long)in_sizes[0];
    long long n4 = n / 4;

    long long n4s = (n4 + 7) / 8;                       // sampled float4 chunks
    unsigned long long sc = (unsigned long long)(n4s * 4);
    unsigned long long ks = (unsigned long long)(0.25 * (double)sc);
    if (ks < 1) ks = 1;
    long long kk = (long long)(0.25 * (double)n);
    if (kk < 1) kk = 1;

    k_zero  <<<64, 256>>>();
    k_sample<<<256, 256>>>((const float4*)pred, (const float4*)targ, n4);
    k_select<<<1, 1024>>>(ks);
    k_main  <<<592, 512>>>((const float4*)pred, (const float4*)targ, n4, n);
    k_final <<<1, 512>>>(kk, (float*)d_out);
}

// round 4
// speedup vs baseline: 4.7562x; 4.7562x over previous
#include <cuda_runtime.h>

#define HIST_SHIFT 18
#define HIST_N     16384          // bits >> 18  (5 mantissa bits resolution)
#define HISTW_N    8192           // packed 2x16-bit counters
#define SUB_SHIFT  8              // 256-ulp sub-buckets (2^-15 relative)
#define SUB_N      8192
#define MARGIN     2
#define SAMPLE_STRIDE 32          // sample every 32nd float4 chunk (1/32)

__device__ unsigned int       g_hist[HIST_N];
__device__ unsigned int       g_sub[SUB_N];
__device__ double             g_sum;
__device__ unsigned long long g_cnt;
__device__ unsigned int       g_ctrl[4];   // [0]=base_bits [1]=hi_bits [2]=nsub

__device__ __forceinline__ float bce_loss(float x, float t) {
    float a  = fabsf(x);
    float sp = log1pf(__expf(-a));
    float l  = fmaxf(x, 0.0f) - x * t + sp;
    return fmaxf(l, 0.0f);
}

// ---------------- K0: zero scratch ----------------
__global__ void k_zero() {
    int i  = blockIdx.x * blockDim.x + threadIdx.x;
    int nt = gridDim.x * blockDim.x;
    for (int j = i; j < HIST_N; j += nt) g_hist[j] = 0u;
    for (int j = i; j < SUB_N;  j += nt) g_sub[j]  = 0u;
    if (i == 0) { g_sum = 0.0; g_cnt = 0ull; }
}

// ---------------- K1: sampled histogram, smem-privatized ----------------
__global__ void __launch_bounds__(512) k_sample(const float4* __restrict__ p,
                                                const float4* __restrict__ t,
                                                long long n4) {
    __shared__ unsigned sh[HISTW_N];    // 2 x u16 counters per word
    for (int j = threadIdx.x; j < HISTW_N; j += 512) sh[j] = 0u;
    __syncthreads();

    long long nchunks = n4 / SAMPLE_STRIDE;
    long long stride  = (long long)gridDim.x * blockDim.x;
    for (long long s = blockIdx.x * (long long)blockDim.x + threadIdx.x;
         s < nchunks; s += stride) {
        long long idx = s * SAMPLE_STRIDE;
        float4 xp = p[idx];
        float4 xt = t[idx];
        unsigned b;
        b = __float_as_uint(bce_loss(xp.x, xt.x)) >> HIST_SHIFT;
        atomicAdd(&sh[b >> 1], (b & 1u) ? 65536u : 1u);
        b = __float_as_uint(bce_loss(xp.y, xt.y)) >> HIST_SHIFT;
        atomicAdd(&sh[b >> 1], (b & 1u) ? 65536u : 1u);
        b = __float_as_uint(bce_loss(xp.z, xt.z)) >> HIST_SHIFT;
        atomicAdd(&sh[b >> 1], (b & 1u) ? 65536u : 1u);
        b = __float_as_uint(bce_loss(xp.w, xt.w)) >> HIST_SHIFT;
        atomicAdd(&sh[b >> 1], (b & 1u) ? 65536u : 1u);
    }
    __syncthreads();

    for (int j = threadIdx.x; j < HISTW_N; j += 512) {
        unsigned c = sh[j];
        if (c & 0xFFFFu) atomicAdd(&g_hist[2 * j],     c & 0xFFFFu);
        if (c >> 16)     atomicAdd(&g_hist[2 * j + 1], c >> 16);
    }
}

// ---------------- K2: sample quantile bucket -> window ----------------
__global__ void __launch_bounds__(512) k_select(unsigned long long ks) {
    __shared__ unsigned long long suf[512];
    int tid = threadIdx.x;

    unsigned v[32];
    unsigned long long s = 0;
    int cbase = tid * 32;
    #pragma unroll
    for (int j = 0; j < 32; j++) { v[j] = g_hist[cbase + j]; s += v[j]; }
    suf[tid] = s;
    __syncthreads();
    for (int off = 1; off < 512; off <<= 1) {   // inclusive suffix scan
        unsigned long long add = (tid + off < 512) ? suf[tid + off] : 0ull;
        __syncthreads();
        suf[tid] += add;
        __syncthreads();
    }
    unsigned long long nxt = (tid < 511) ? suf[tid + 1] : 0ull;
    if (suf[tid] >= ks && nxt < ks) {
        // this thread's chunk contains the quantile bin; rescan registers
        unsigned long long cum = nxt;
        int bstar = cbase;
        #pragma unroll
        for (int j = 31; j >= 0; j--) {
            cum += v[j];
            if (cum >= ks) { bstar = cbase + j; break; }
        }
        int blo = (bstar >= MARGIN) ? bstar - MARGIN : 0;
        int bhi = (bstar + MARGIN <= HIST_N - 1) ? bstar + MARGIN : HIST_N - 1;
        g_ctrl[0] = (unsigned)blo << HIST_SHIFT;
        g_ctrl[1] = (unsigned)(bhi + 1) << HIST_SHIFT;
        g_ctrl[2] = (((unsigned)(bhi - blo + 1)) << HIST_SHIFT) >> SUB_SHIFT;
    }
}

// ---------------- K3: main exact pass (2-way unrolled) ----------------
__device__ __forceinline__ void acc_elem(float x, float t, unsigned base, unsigned hi,
                                         double& lsum, unsigned& lcnt) {
    float v = bce_loss(x, t);
    unsigned b = __float_as_uint(v);
    if (b >= hi)        { lsum += v; lcnt++; }
    else if (b >= base) atomicAdd(&g_sub[(b - base) >> SUB_SHIFT], 1u);
}

__global__ void __launch_bounds__(512) k_main(const float4* __restrict__ p,
                                              const float4* __restrict__ t,
                                              long long n4, long long n) {
    const unsigned base = g_ctrl[0];
    const unsigned hi   = g_ctrl[1];
    double   lsum = 0.0;
    unsigned lcnt = 0u;

    long long stride = (long long)gridDim.x * blockDim.x;
    long long i = blockIdx.x * (long long)blockDim.x + threadIdx.x;

    for (; i + stride < n4; i += 2 * stride) {
        float4 a0 = p[i];
        float4 a1 = p[i + stride];
        float4 b0 = t[i];
        float4 b1 = t[i + stride];
        acc_elem(a0.x, b0.x, base, hi, lsum, lcnt);
        acc_elem(a0.y, b0.y, base, hi, lsum, lcnt);
        acc_elem(a0.z, b0.z, base, hi, lsum, lcnt);
        acc_elem(a0.w, b0.w, base, hi, lsum, lcnt);
        acc_elem(a1.x, b1.x, base, hi, lsum, lcnt);
        acc_elem(a1.y, b1.y, base, hi, lsum, lcnt);
        acc_elem(a1.z, b1.z, base, hi, lsum, lcnt);
        acc_elem(a1.w, b1.w, base, hi, lsum, lcnt);
    }
    for (; i < n4; i += stride) {
        float4 a0 = p[i];
        float4 b0 = t[i];
        acc_elem(a0.x, b0.x, base, hi, lsum, lcnt);
        acc_elem(a0.y, b0.y, base, hi, lsum, lcnt);
        acc_elem(a0.z, b0.z, base, hi, lsum, lcnt);
        acc_elem(a0.w, b0.w, base, hi, lsum, lcnt);
    }
    if (blockIdx.x == 0 && threadIdx.x == 0) {  // scalar tail
        const float* ps = (const float*)p;
        const float* ts = (const float*)t;
        for (long long j = n4 * 4; j < n; j++)
            acc_elem(ps[j], ts[j], base, hi, lsum, lcnt);
    }

    for (int o = 16; o; o >>= 1) {
        lsum += __shfl_down_sync(0xffffffffu, lsum, o);
        lcnt += __shfl_down_sync(0xffffffffu, lcnt, o);
    }
    __shared__ double   ws[16];
    __shared__ unsigned wc[16];
    int wid = threadIdx.x >> 5, lane = threadIdx.x & 31;
    if (lane == 0) { ws[wid] = lsum; wc[wid] = lcnt; }
    __syncthreads();
    if (wid == 0) {
        double   v = (lane < 16) ? ws[lane] : 0.0;
        unsigned c = (lane < 16) ? wc[lane] : 0u;
        for (int o = 8; o; o >>= 1) {
            v += __shfl_down_sync(0xffffffffu, v, o);
            c += __shfl_down_sync(0xffffffffu, c, o);
        }
        if (lane == 0) {
            atomicAdd(&g_sum, v);
            atomicAdd(&g_cnt, (unsigned long long)c);
        }
    }
}

// ---------------- K4: finalize ----------------
__global__ void __launch_bounds__(512) k_final(long long k, float* __restrict__ out) {
    __shared__ unsigned long long sufc[512];
    __shared__ double             sufw[512];
    int tid = threadIdx.x;
    unsigned base = g_ctrl[0];
    int nsub = (int)g_ctrl[2];
    int per  = (nsub + 511) / 512;

    unsigned cs_loc[16];            // per <= (5<<18)>>8 / 512 = 10
    unsigned long long c = 0ull;
    double             w = 0.0;
    for (int j = 0; j < per; j++) {
        int s = tid * per + j;
        unsigned cs = (s < nsub) ? g_sub[s] : 0u;
        if (j < 16) cs_loc[j] = cs;
        c += cs;
        if (cs)
            w += (double)cs *
                 (double)__uint_as_float(base + ((unsigned)s << SUB_SHIFT) +
                                         (1u << (SUB_SHIFT - 1)));
    }
    sufc[tid] = c; sufw[tid] = w;
    __syncthreads();
    for (int off = 1; off < 512; off <<= 1) {
        unsigned long long ac = (tid + off < 512) ? sufc[tid + off] : 0ull;
        double             aw = (tid + off < 512) ? sufw[tid + off] : 0.0;
        __syncthreads();
        sufc[tid] += ac; sufw[tid] += aw;
        __syncthreads();
    }

    double    sum_gt = g_sum;
    long long cnt    = (long long)g_cnt;
    long long r      = k - cnt;

    if (r <= 0) {
        if (tid == 0) {
            double edge = (double)__uint_as_float(g_ctrl[1]);
            out[0] = (float)((sum_gt + (double)r * edge) / (double)k);
        }
        return;
    }
    if ((unsigned long long)r > sufc[0]) {
        if (tid == 0) {
            double res = (sum_gt + sufw[0] +
                          (double)(r - (long long)sufc[0]) *
                          (double)__uint_as_float(base)) / (double)k;
            out[0] = (float)res;
        }
        return;
    }

    unsigned long long nxtc = (tid < 511) ? sufc[tid + 1] : 0ull;
    double             nxtw = (tid < 511) ? sufw[tid + 1] : 0.0;
    if (sufc[tid] >= (unsigned long long)r && nxtc < (unsigned long long)r) {
        unsigned long long cum = nxtc;
        double             acc = nxtw;
        for (int j = per - 1; j >= 0; j--) {
            int s = tid * per + j;
            if (s >= nsub) continue;
            unsigned cs = (j < 16) ? cs_loc[j] : g_sub[s];
            double mid = (double)__uint_as_float(base + ((unsigned)s << SUB_SHIFT) +
                                                 (1u << (SUB_SHIFT - 1)));
            if (cum + cs >= (unsigned long long)r) {
                acc += (double)((unsigned long long)r - cum) * mid;
                out[0] = (float)((sum_gt + acc) / (double)k);
                break;
            } else {
                acc += (double)cs * mid;
                cum += cs;
            }
        }
    }
}

// ---------------- host ----------------
extern "C" void kernel_launch(void* const* d_in, const int* in_sizes, int n_in,
                              void* d_out, int out_size) {
    const float* pred = (const float*)d_in[0];
    const float* targ = (const float*)d_in[1];
    long long n  = (long long)in_sizes[0];
    long long n4 = n / 4;

    long long nchunks = n4 / SAMPLE_STRIDE;
    if (nchunks < 1) nchunks = 1;
    unsigned long long sc = (unsigned long long)(nchunks * 4);
    unsigned long long ks = (unsigned long long)(0.25 * (double)sc);
    if (ks < 1) ks = 1;
    long long kk = (long long)(0.25 * (double)n);
    if (kk < 1) kk = 1;

    k_zero  <<<32, 256>>>();
    k_sample<<<148, 512>>>((const float4*)pred, (const float4*)targ, n4);
    k_select<<<1, 512>>>(ks);
    k_main  <<<1184, 512>>>((const float4*)pred, (const float4*)targ, n4, n);
    k_final <<<1, 512>>>(kk, (float*)d_out);
}

// round 5
// speedup vs baseline: 7.0932x; 1.4914x over previous
#include <cuda_runtime.h>

#define HIST_SHIFT 18
#define HIST_N     16384
#define HISTW_N    8192
#define SUB_SHIFT  8
#define SUB_N      8192
#define MARGIN     2
#define SAMPLE_DIV 64            // sample first 1/64 of float4 chunks (contiguous)

__device__ unsigned int       g_hist[HIST_N];   // zero at load; k_select re-zeroes
__device__ unsigned int       g_sub[SUB_N];     // zero at load; k_final re-zeroes
__device__ double             g_sum;            // k_final re-zeroes
__device__ unsigned long long g_cnt;            // k_final re-zeroes
__device__ unsigned int       g_ctrl[4];        // [0]=base_bits [1]=hi_bits [2]=nsub

__device__ __forceinline__ float bce_loss(float x, float t) {
    // loss = max(x,0) - x*t + log(1+exp(-|x|)), all-MUFU softplus
    float e  = exp2f(fabsf(x) * -1.44269504f);          // FMUL(|x|) + MUFU.EX2
    float lg = __log2f(1.0f + e);                       // FADD + MUFU.LG2
    float r  = __fmaf_rn(-x, t, fmaxf(x, 0.0f));        // FMNMX + FFMA
    return fmaxf(__fmaf_rn(0.69314718f, lg, r), 0.0f);  // FFMA + FMNMX
}

// ---------------- K1: sampled histogram (contiguous prefix, smem-privatized) --
__global__ void __launch_bounds__(512) k_sample(const float4* __restrict__ p,
                                                const float4* __restrict__ t,
                                                int nchunks) {
    __shared__ unsigned sh[HISTW_N];    // 2 x u16 counters per word
    for (int j = threadIdx.x; j < HISTW_N; j += 512) sh[j] = 0u;
    __syncthreads();

    int stride = gridDim.x * blockDim.x;
    for (int s = blockIdx.x * blockDim.x + threadIdx.x; s < nchunks; s += stride) {
        float4 xp = p[s];
        float4 xt = t[s];
        unsigned b;
        b = __float_as_uint(bce_loss(xp.x, xt.x)) >> HIST_SHIFT;
        atomicAdd(&sh[b >> 1], (b & 1u) ? 65536u : 1u);
        b = __float_as_uint(bce_loss(xp.y, xt.y)) >> HIST_SHIFT;
        atomicAdd(&sh[b >> 1], (b & 1u) ? 65536u : 1u);
        b = __float_as_uint(bce_loss(xp.z, xt.z)) >> HIST_SHIFT;
        atomicAdd(&sh[b >> 1], (b & 1u) ? 65536u : 1u);
        b = __float_as_uint(bce_loss(xp.w, xt.w)) >> HIST_SHIFT;
        atomicAdd(&sh[b >> 1], (b & 1u) ? 65536u : 1u);
    }
    __syncthreads();

    for (int j = threadIdx.x; j < HISTW_N; j += 512) {
        unsigned c = sh[j];
        if (c & 0xFFFFu) atomicAdd(&g_hist[2 * j],     c & 0xFFFFu);
        if (c >> 16)     atomicAdd(&g_hist[2 * j + 1], c >> 16);
    }
}

// ---------------- K2: sample quantile bucket -> window; zero g_hist ----------
__global__ void __launch_bounds__(512) k_select(unsigned long long ks) {
    __shared__ unsigned long long suf[512];
    int tid = threadIdx.x;

    unsigned v[32];
    unsigned long long s = 0;
    int cbase = tid * 32;
    #pragma unroll
    for (int j = 0; j < 32; j++) { v[j] = g_hist[cbase + j]; s += v[j]; }
    #pragma unroll
    for (int j = 0; j < 32; j++) g_hist[cbase + j] = 0u;   // self-clean for next call
    suf[tid] = s;
    __syncthreads();
    for (int off = 1; off < 512; off <<= 1) {   // inclusive suffix scan
        unsigned long long add = (tid + off < 512) ? suf[tid + off] : 0ull;
        __syncthreads();
        suf[tid] += add;
        __syncthreads();
    }
    unsigned long long nxt = (tid < 511) ? suf[tid + 1] : 0ull;
    if (suf[tid] >= ks && nxt < ks) {
        unsigned long long cum = nxt;
        int bstar = cbase;
        #pragma unroll
        for (int j = 31; j >= 0; j--) {
            cum += v[j];
            if (cum >= ks) { bstar = cbase + j; break; }
        }
        int blo = (bstar >= MARGIN) ? bstar - MARGIN : 0;
        int bhi = (bstar + MARGIN <= HIST_N - 1) ? bstar + MARGIN : HIST_N - 1;
        g_ctrl[0] = (unsigned)blo << HIST_SHIFT;
        g_ctrl[1] = (unsigned)(bhi + 1) << HIST_SHIFT;
        g_ctrl[2] = (((unsigned)(bhi - blo + 1)) << HIST_SHIFT) >> SUB_SHIFT;
    }
}

// ---------------- K3: main exact pass (float accumulators, 32-bit idx) -------
__device__ __forceinline__ void acc_elem(float x, float t, unsigned base, unsigned hi,
                                         float& fsum, unsigned& lcnt) {
    float v = bce_loss(x, t);
    unsigned b = __float_as_uint(v);
    if (b >= hi)        { fsum += v; lcnt++; }
    else if (b >= base) atomicAdd(&g_sub[(b - base) >> SUB_SHIFT], 1u);
}

__global__ void __launch_bounds__(512) k_main(const float4* __restrict__ p,
                                              const float4* __restrict__ t,
                                              int n4, long long n) {
    const unsigned base = g_ctrl[0];
    const unsigned hi   = g_ctrl[1];
    float    fsum = 0.0f;
    unsigned lcnt = 0u;

    unsigned stride = gridDim.x * blockDim.x;
    unsigned i = blockIdx.x * blockDim.x + threadIdx.x;

    for (; i + stride < (unsigned)n4; i += 2u * stride) {
        float4 a0 = p[i];
        float4 b0 = t[i];
        float4 a1 = p[i + stride];
        float4 b1 = t[i + stride];
        acc_elem(a0.x, b0.x, base, hi, fsum, lcnt);
        acc_elem(a0.y, b0.y, base, hi, fsum, lcnt);
        acc_elem(a0.z, b0.z, base, hi, fsum, lcnt);
        acc_elem(a0.w, b0.w, base, hi, fsum, lcnt);
        acc_elem(a1.x, b1.x, base, hi, fsum, lcnt);
        acc_elem(a1.y, b1.y, base, hi, fsum, lcnt);
        acc_elem(a1.z, b1.z, base, hi, fsum, lcnt);
        acc_elem(a1.w, b1.w, base, hi, fsum, lcnt);
    }
    for (; i < (unsigned)n4; i += stride) {
        float4 a0 = p[i];
        float4 b0 = t[i];
        acc_elem(a0.x, b0.x, base, hi, fsum, lcnt);
        acc_elem(a0.y, b0.y, base, hi, fsum, lcnt);
        acc_elem(a0.z, b0.z, base, hi, fsum, lcnt);
        acc_elem(a0.w, b0.w, base, hi, fsum, lcnt);
    }
    if (blockIdx.x == 0 && threadIdx.x == 0) {   // scalar tail (n % 4)
        const float* ps = (const float*)p;
        const float* ts = (const float*)t;
        for (long long j = (long long)n4 * 4; j < n; j++)
            acc_elem(ps[j], ts[j], base, hi, fsum, lcnt);
    }

    // warp reduce (float)
    for (int o = 16; o; o >>= 1) {
        fsum += __shfl_down_sync(0xffffffffu, fsum, o);
        lcnt += __shfl_down_sync(0xffffffffu, lcnt, o);
    }
    __shared__ float    ws[16];
    __shared__ unsigned wc[16];
    int wid = threadIdx.x >> 5, lane = threadIdx.x & 31;
    if (lane == 0) { ws[wid] = fsum; wc[wid] = lcnt; }
    __syncthreads();
    if (wid == 0) {
        float    v = (lane < 16) ? ws[lane] : 0.0f;
        unsigned c = (lane < 16) ? wc[lane] : 0u;
        for (int o = 8; o; o >>= 1) {
            v += __shfl_down_sync(0xffffffffu, v, o);
            c += __shfl_down_sync(0xffffffffu, c, o);
        }
        if (lane == 0) {
            atomicAdd(&g_sum, (double)v);
            atomicAdd(&g_cnt, (unsigned long long)c);
        }
    }
}

// ---------------- K4: finalize; self-clean g_sub/g_sum/g_cnt -----------------
__global__ void __launch_bounds__(512) k_final(long long k, float* __restrict__ out) {
    __shared__ unsigned long long sufc[512];
    __shared__ double             sufw[512];
    int tid = threadIdx.x;
    unsigned base = g_ctrl[0];
    int nsub = (int)g_ctrl[2];                 // <= 5120
    int per  = (nsub + 511) / 512;             // <= 10

    unsigned cs_loc[12];
    unsigned long long c = 0ull;
    double             w = 0.0;
    for (int j = 0; j < per; j++) {
        int s = tid * per + j;
        unsigned cs = (s < nsub) ? g_sub[s] : 0u;
        if (s < nsub) g_sub[s] = 0u;           // self-clean
        cs_loc[j] = cs;
        c += cs;
        if (cs)
            w += (double)cs *
                 (double)__uint_as_float(base + ((unsigned)s << SUB_SHIFT) +
                                         (1u << (SUB_SHIFT - 1)));
    }
    sufc[tid] = c; sufw[tid] = w;
    __syncthreads();
    for (int off = 1; off < 512; off <<= 1) {
        unsigned long long ac = (tid + off < 512) ? sufc[tid + off] : 0ull;
        double             aw = (tid + off < 512) ? sufw[tid + off] : 0.0;
        __syncthreads();
        sufc[tid] += ac; sufw[tid] += aw;
        __syncthreads();
    }

    double    sum_gt = g_sum;
    long long cnt    = (long long)g_cnt;
    __syncthreads();
    if (tid == 0) { g_sum = 0.0; g_cnt = 0ull; }   // self-clean
    long long r = k - cnt;

    if (r <= 0) {
        if (tid == 0) {
            double edge = (double)__uint_as_float(g_ctrl[1]);
            out[0] = (float)((sum_gt + (double)r * edge) / (double)k);
        }
        return;
    }
    if ((unsigned long long)r > sufc[0]) {
        if (tid == 0) {
            double res = (sum_gt + sufw[0] +
                          (double)(r - (long long)sufc[0]) *
                          (double)__uint_as_float(base)) / (double)k;
            out[0] = (float)res;
        }
        return;
    }

    unsigned long long nxtc = (tid < 511) ? sufc[tid + 1] : 0ull;
    double             nxtw = (tid < 511) ? sufw[tid + 1] : 0.0;
    if (sufc[tid] >= (unsigned long long)r && nxtc < (unsigned long long)r) {
        unsigned long long cum = nxtc;
        double             acc = nxtw;
        for (int j = per - 1; j >= 0; j--) {
            int s = tid * per + j;
            if (s >= nsub) continue;
            unsigned cs = cs_loc[j];
            double mid = (double)__uint_as_float(base + ((unsigned)s << SUB_SHIFT) +
                                                 (1u << (SUB_SHIFT - 1)));
            if (cum + cs >= (unsigned long long)r) {
                acc += (double)((unsigned long long)r - cum) * mid;
                out[0] = (float)((sum_gt + acc) / (double)k);
                break;
            } else {
                acc += (double)cs * mid;
                cum += cs;
            }
        }
    }
}

// ---------------- host ----------------
extern "C" void kernel_launch(void* const* d_in, const int* in_sizes, int n_in,
                              void* d_out, int out_size) {
    const float* pred = (const float*)d_in[0];
    const float* targ = (const float*)d_in[1];
    long long n  = (long long)in_sizes[0];
    int       n4 = (int)(n / 4);

    int nchunks = n4 / SAMPLE_DIV;
    if (nchunks < 1) nchunks = (n4 > 0) ? n4 : 1;
    unsigned long long sc = (unsigned long long)nchunks * 4ull;
    unsigned long long ks = (unsigned long long)(0.25 * (double)sc);
    if (ks < 1) ks = 1;
    long long kk = (long long)(0.25 * (double)n);
    if (kk < 1) kk = 1;

    k_sample<<<148, 512>>>((const float4*)pred, (const float4*)targ, nchunks);
    k_select<<<1, 512>>>(ks);
    k_main  <<<1184, 512>>>((const float4*)pred, (const float4*)targ, n4, n);
    k_final <<<1, 512>>>(kk, (float*)d_out);
}